// round 15
// baseline (speedup 1.0000x reference)
#include <cuda_runtime.h>
#include <cuda_bf16.h>
#include <cstdint>
#include <math.h>

#define NB   8
#define EE   256
#define LL   64
#define SS   4096
#define QKV  768

// ---------------- scratch ----------------
__device__ float g_Y[NB * QKV * SS];
__device__ float g_qland[NB * LL * EE];
__device__ float g_kland[NB * LL * EE];
__device__ float g_S1[NB * SS * LL];
__device__ float g_pmax[NB * 8 * LL];
__device__ float g_psum[NB * 8 * LL];
__device__ float g_m[NB * LL];
__device__ float g_sinv[NB * LL];
__device__ float g_S3[NB * LL * SS];
__device__ float g_T3p[NB * 8 * LL * EE];
__device__ float g_T3[NB * LL * EE];

// split-bf16 operands
__device__ __nv_bfloat16 g_wqh[QKV * 256], g_wql[QKV * 256];
__device__ __nv_bfloat16 g_woh[256 * 256], g_wol[256 * 256];
__device__ __nv_bfloat16 g_xh[NB * SS * 256], g_xl[NB * SS * 256];
__device__ __nv_bfloat16 g_obh[NB * 256 * SS], g_obl[NB * 256 * SS];   // O raw-view [e2][s2]
__device__ __nv_bfloat16 g_qbh[NB * SS * 256], g_qbl[NB * SS * 256];
__device__ __nv_bfloat16 g_kbh[NB * SS * 256], g_kbl[NB * SS * 256];
__device__ __nv_bfloat16 g_vth[NB * 256 * SS], g_vtl[NB * 256 * SS];
__device__ __nv_bfloat16 g_qlbh[NB * LL * 256], g_qlbl[NB * LL * 256];
__device__ __nv_bfloat16 g_klbh[NB * LL * 256], g_klbl[NB * LL * 256];
__device__ __nv_bfloat16 g_M2h[NB * 256 * LL], g_M2l[NB * 256 * LL];

__device__ __forceinline__ uint32_t smem_u32(const void* p) {
    uint32_t a;
    asm("{ .reg .u64 t; cvta.to.shared.u64 t, %1; cvt.u32.u64 %0, t; }" : "=r"(a) : "l"(p));
    return a;
}
__device__ __forceinline__ void mma_bf16(float* d, uint32_t a0, uint32_t a1, uint32_t a2,
                                         uint32_t a3, uint32_t b0, uint32_t b1) {
    asm volatile(
        "mma.sync.aligned.m16n8k16.row.col.f32.bf16.bf16.f32 "
        "{%0,%1,%2,%3}, {%4,%5,%6,%7}, {%8,%9}, {%0,%1,%2,%3};"
        : "+f"(d[0]), "+f"(d[1]), "+f"(d[2]), "+f"(d[3])
        : "r"(a0), "r"(a1), "r"(a2), "r"(a3), "r"(b0), "r"(b1));
}
#define LDSM_X4(r0, r1, r2, r3, addr) \
    asm volatile("ldmatrix.sync.aligned.m8n8.x4.shared.b16 {%0,%1,%2,%3}, [%4];" \
        : "=r"(r0), "=r"(r1), "=r"(r2), "=r"(r3) : "r"(addr))
#define LDSM_X4T(r0, r1, r2, r3, addr) \
    asm volatile("ldmatrix.sync.aligned.m8n8.x4.trans.shared.b16 {%0,%1,%2,%3}, [%4];" \
        : "=r"(r0), "=r"(r1), "=r"(r2), "=r"(r3) : "r"(addr))
__device__ __forceinline__ uint32_t pack2(float a, float b) {
    __nv_bfloat162 h = __floats2bfloat162_rn(a, b);
    return *(uint32_t*)&h;
}
#define CPA16(d, s) asm volatile("cp.async.cg.shared.global [%0], [%1], 16;" :: "r"(d), "l"(s))
#define CPA_COMMIT() asm volatile("cp.async.commit_group;" ::: "memory")
#define CPA_WAIT0()  asm volatile("cp.async.wait_group 0;" ::: "memory")
#define CPA_WAIT1()  asm volatile("cp.async.wait_group 1;" ::: "memory")

// ================= big split-bf16 GEMM, K-major B (verified R14) =================
#define MG_STAGE 40960
#define MG_SMEM  (2 * MG_STAGE)
__global__ __launch_bounds__(256, 2) void mma_gemm_k(
    const __nv_bfloat16* __restrict__ Ah, const __nv_bfloat16* __restrict__ Al,
    const __nv_bfloat16* __restrict__ Bh, const __nv_bfloat16* __restrict__ Bl,
    float* __restrict__ C, const float* __restrict__ bias,
    long bStride, long cStride)
{
    extern __shared__ char smc[];
    const int tid = threadIdx.x;
    const int lane = tid & 31, wid = tid >> 5;
    const int wm = wid >> 2, ws = wid & 3;
    const int gid = lane >> 2, tg = lane & 3;
    const int n = blockIdx.z;
    const int m0 = blockIdx.y * 128, s0 = blockIdx.x * 128;

    const __nv_bfloat16* gsrc[4];
    gsrc[0] = Ah + (long)m0 * 256;
    gsrc[1] = Al + (long)m0 * 256;
    gsrc[2] = Bh + (long)n * bStride + (long)s0 * 256;
    gsrc[3] = Bl + (long)n * bStride + (long)s0 * 256;

    const int a_lrow = lane & 15;
    const uint32_t a_kadj = ((lane >> 4) << 4);
    const int b_lrow = (lane & 7) + ((lane >> 4) << 3);
    const uint32_t b_kadj = (((lane >> 3) & 1) << 4);

    float acc[4][4][4];
#pragma unroll
    for (int a = 0; a < 4; a++)
#pragma unroll
        for (int b = 0; b < 4; b++)
#pragma unroll
            for (int c = 0; c < 4; c++) acc[a][b][c] = 0.f;

    auto issue = [&](int c, int buf) {
#pragma unroll
        for (int it = 0; it < 8; it++) {
            int idx = tid + it * 256;
            int mat = idx >> 9, rr = (idx >> 2) & 127, seg = idx & 3;
            uint32_t d = smem_u32(smc + buf * MG_STAGE + mat * 10240 + rr * 80 + seg * 16);
            const __nv_bfloat16* s = gsrc[mat] + rr * 256 + c * 32 + seg * 8;
            CPA16(d, s);
        }
        CPA_COMMIT();
    };

    issue(0, 0);
    for (int c = 0; c < 8; c++) {
        if (c < 7) { issue(c + 1, (c + 1) & 1); CPA_WAIT1(); }
        else CPA_WAIT0();
        __syncthreads();
        const uint32_t stb = smem_u32(smc + (c & 1) * MG_STAGE);
#pragma unroll
        for (int ks = 0; ks < 2; ks++) {
            uint32_t bh[4][2], bl[4][2];
#pragma unroll
            for (int pr = 0; pr < 2; pr++) {
                int nrow = ws * 32 + pr * 16 + b_lrow;
                uint32_t boff = stb + 20480 + nrow * 80 + ks * 32 + b_kadj;
                LDSM_X4(bh[2 * pr][0], bh[2 * pr][1], bh[2 * pr + 1][0], bh[2 * pr + 1][1], boff);
                LDSM_X4(bl[2 * pr][0], bl[2 * pr][1], bl[2 * pr + 1][0], bl[2 * pr + 1][1],
                        boff + 10240);
            }
#pragma unroll
            for (int mt = 0; mt < 4; mt++) {
                int arow = wm * 64 + mt * 16 + a_lrow;
                uint32_t aoff = stb + arow * 80 + ks * 32 + a_kadj;
                uint32_t ah0, ah1, ah2, ah3, al0, al1, al2, al3;
                LDSM_X4(ah0, ah1, ah2, ah3, aoff);
                LDSM_X4(al0, al1, al2, al3, aoff + 10240);
#pragma unroll
                for (int nt = 0; nt < 4; nt++) {
                    mma_bf16(acc[mt][nt], ah0, ah1, ah2, ah3, bh[nt][0], bh[nt][1]);
                    mma_bf16(acc[mt][nt], ah0, ah1, ah2, ah3, bl[nt][0], bl[nt][1]);
                    mma_bf16(acc[mt][nt], al0, al1, al2, al3, bh[nt][0], bh[nt][1]);
                }
            }
        }
        __syncthreads();
    }

    float* Cn = C + (long)n * cStride;
#pragma unroll
    for (int mt = 0; mt < 4; mt++) {
        int r0 = m0 + wm * 64 + mt * 16 + gid;
        float b0v = bias[r0], b1v = bias[r0 + 8];
#pragma unroll
        for (int nt = 0; nt < 4; nt++) {
            int col = s0 + ws * 32 + nt * 8 + tg * 2;
            *(float2*)(Cn + (long)r0 * 4096 + col) =
                make_float2(acc[mt][nt][0] + b0v, acc[mt][nt][1] + b0v);
            *(float2*)(Cn + (long)(r0 + 8) * 4096 + col) =
                make_float2(acc[mt][nt][2] + b1v, acc[mt][nt][3] + b1v);
        }
    }
}

// ================= GEMM variant: B stored [k][s] row-major, loaded via ldmatrix.trans =====
// C[n][m][s] = sum_k A[m][k] * Bt[n][k][s] + bias[m]
#define BT_BROW 272
#define BT_MAT  8704            // 32 rows * 272
#define BT_STAGE (2 * 10240 + 2 * BT_MAT)   // 37888
#define BT_SMEM  (2 * BT_STAGE)
__global__ __launch_bounds__(256, 2) void mma_gemm_bt(
    const __nv_bfloat16* __restrict__ Ah, const __nv_bfloat16* __restrict__ Al,
    const __nv_bfloat16* __restrict__ Bth, const __nv_bfloat16* __restrict__ Btl,
    float* __restrict__ C, const float* __restrict__ bias,
    long bStride, long cStride)
{
    extern __shared__ char smc[];
    const int tid = threadIdx.x;
    const int lane = tid & 31, wid = tid >> 5;
    const int wm = wid >> 2, ws = wid & 3;
    const int gid = lane >> 2, tg = lane & 3;
    const int n = blockIdx.z;
    const int m0 = blockIdx.y * 128, s0 = blockIdx.x * 128;

    const __nv_bfloat16* Asrc[2] = {Ah + (long)m0 * 256, Al + (long)m0 * 256};
    const __nv_bfloat16* Bsrc[2] = {Bth + (long)n * bStride, Btl + (long)n * bStride};

    const int a_lrow = lane & 15;
    const uint32_t a_kadj = ((lane >> 4) << 4);
    // trans-B lane address components: row = (lane&7) + ((lane>>3)&1)*8, col + (lane>>4)*16B
    const int bt_row = (lane & 7) + ((lane >> 3) & 1) * 8;
    const uint32_t bt_cadj = ((lane >> 4) << 4);

    float acc[4][4][4];
#pragma unroll
    for (int a = 0; a < 4; a++)
#pragma unroll
        for (int b = 0; b < 4; b++)
#pragma unroll
            for (int c = 0; c < 4; c++) acc[a][b][c] = 0.f;

    auto issue = [&](int c, int buf) {
#pragma unroll
        for (int it = 0; it < 8; it++) {
            int idx = tid + it * 256;
            uint32_t d; const __nv_bfloat16* s;
            if (idx < 1024) {
                int mat = idx >> 9, rr = (idx >> 2) & 127, seg = idx & 3;
                d = smem_u32(smc + buf * BT_STAGE + mat * 10240 + rr * 80 + seg * 16);
                s = Asrc[mat] + rr * 256 + c * 32 + seg * 8;
            } else {
                int j = idx - 1024;
                int mat = j >> 9, r = (j >> 4) & 31, seg = j & 15;
                d = smem_u32(smc + buf * BT_STAGE + 20480 + mat * BT_MAT + r * BT_BROW + seg * 16);
                s = Bsrc[mat] + (long)(c * 32 + r) * 4096 + s0 + seg * 8;
            }
            CPA16(d, s);
        }
        CPA_COMMIT();
    };

    issue(0, 0);
    for (int c = 0; c < 8; c++) {
        if (c < 7) { issue(c + 1, (c + 1) & 1); CPA_WAIT1(); }
        else CPA_WAIT0();
        __syncthreads();
        const uint32_t stb = smem_u32(smc + (c & 1) * BT_STAGE);
#pragma unroll
        for (int ks = 0; ks < 2; ks++) {
            uint32_t bh[4][2], bl[4][2];
#pragma unroll
            for (int pr = 0; pr < 2; pr++) {
                uint32_t boff = stb + 20480 + (ks * 16 + bt_row) * BT_BROW
                              + ws * 64 + pr * 32 + bt_cadj;
                LDSM_X4T(bh[2 * pr][0], bh[2 * pr][1], bh[2 * pr + 1][0], bh[2 * pr + 1][1], boff);
                LDSM_X4T(bl[2 * pr][0], bl[2 * pr][1], bl[2 * pr + 1][0], bl[2 * pr + 1][1],
                         boff + BT_MAT);
            }
#pragma unroll
            for (int mt = 0; mt < 4; mt++) {
                int arow = wm * 64 + mt * 16 + a_lrow;
                uint32_t aoff = stb + arow * 80 + ks * 32 + a_kadj;
                uint32_t ah0, ah1, ah2, ah3, al0, al1, al2, al3;
                LDSM_X4(ah0, ah1, ah2, ah3, aoff);
                LDSM_X4(al0, al1, al2, al3, aoff + 10240);
#pragma unroll
                for (int nt = 0; nt < 4; nt++) {
                    mma_bf16(acc[mt][nt], ah0, ah1, ah2, ah3, bh[nt][0], bh[nt][1]);
                    mma_bf16(acc[mt][nt], ah0, ah1, ah2, ah3, bl[nt][0], bl[nt][1]);
                    mma_bf16(acc[mt][nt], al0, al1, al2, al3, bh[nt][0], bh[nt][1]);
                }
            }
        }
        __syncthreads();
    }

    float* Cn = C + (long)n * cStride;
#pragma unroll
    for (int mt = 0; mt < 4; mt++) {
        int r0 = m0 + wm * 64 + mt * 16 + gid;
        float b0v = bias[r0], b1v = bias[r0 + 8];
#pragma unroll
        for (int nt = 0; nt < 4; nt++) {
            int col = s0 + ws * 32 + nt * 8 + tg * 2;
            *(float2*)(Cn + (long)r0 * 4096 + col) =
                make_float2(acc[mt][nt][0] + b0v, acc[mt][nt][1] + b0v);
            *(float2*)(Cn + (long)(r0 + 8) * 4096 + col) =
                make_float2(acc[mt][nt][2] + b1v, acc[mt][nt][3] + b1v);
        }
    }
}

// ================= converts =================
__global__ void cvt_w_k(const float* __restrict__ src, __nv_bfloat16* __restrict__ hi,
                        __nv_bfloat16* __restrict__ lo, int nElem)
{
    int i = blockIdx.x * 256 + threadIdx.x;
    if (i < nElem) {
        float v = src[i];
        __nv_bfloat16 h = __float2bfloat16(v);
        hi[i] = h;
        lo[i] = __float2bfloat16(v - __bfloat162float(h));
    }
}

__global__ void tcvt_k(const float* __restrict__ src, __nv_bfloat16* __restrict__ hi,
                       __nv_bfloat16* __restrict__ lo, long srcBatchStride)
{
    __shared__ float t[32][33];
    int n = blockIdx.z;
    const float* S = src + (long)n * srcBatchStride;
    int s0 = blockIdx.x * 32, k0 = blockIdx.y * 32;
    int tx = threadIdx.x, ty = threadIdx.y;
#pragma unroll
    for (int i = 0; i < 32; i += 8) t[ty + i][tx] = S[(long)(k0 + ty + i) * 4096 + s0 + tx];
    __syncthreads();
    long base = (long)n * 1048576;
#pragma unroll
    for (int i = 0; i < 32; i += 8) {
        float v = t[tx][ty + i];
        __nv_bfloat16 h = __float2bfloat16(v);
        long o = base + (long)(s0 + ty + i) * 256 + k0 + tx;
        hi[o] = h;
        lo[o] = __float2bfloat16(v - __bfloat162float(h));
    }
}

// fused: q/k flat-view bf16 converts + landmark means + landmark bf16 converts
__global__ __launch_bounds__(256) void qkland_k()
{
    int n = blockIdx.x, l = blockIdx.y, e = threadIdx.x;
    const float* base = g_Y + (long)n * 3145728 + (long)l * 64 * 768;
    float aq = 0.f, ak = 0.f;
    long obase = ((long)n * 4096 + l * 64) * 256 + e;
#pragma unroll 4
    for (int r = 0; r < 64; r++) {
        float q = base[r * 768 + e];
        float k = base[r * 768 + 256 + e];
        aq += q; ak += k;
        __nv_bfloat16 qh = __float2bfloat16(q);
        __nv_bfloat16 kh = __float2bfloat16(k);
        long o = obase + (long)r * 256;
        g_qbh[o] = qh; g_qbl[o] = __float2bfloat16(q - __bfloat162float(qh));
        g_kbh[o] = kh; g_kbl[o] = __float2bfloat16(k - __bfloat162float(kh));
    }
    int idx = (n * 64 + l) * 256 + e;
    float ql = aq * (1.f / 4096.f), kl = ak * (1.f / 4096.f);
    g_qland[idx] = ql; g_kland[idx] = kl;
    __nv_bfloat16 qlh = __float2bfloat16(ql), klh = __float2bfloat16(kl);
    g_qlbh[idx] = qlh; g_qlbl[idx] = __float2bfloat16(ql - __bfloat162float(qlh));
    g_klbh[idx] = klh; g_klbl[idx] = __float2bfloat16(kl - __bfloat162float(klh));
}

// vT transpose convert
__global__ void vtcvt_k()
{
    __shared__ float t[32][33];
    int n = blockIdx.z;
    int s0 = blockIdx.x * 32, e0 = blockIdx.y * 32;
    int tx = threadIdx.x, ty = threadIdx.y;
    const float* S = g_Y + (long)n * 3145728;
#pragma unroll
    for (int i = 0; i < 32; i += 8)
        t[ty + i][tx] = S[(long)(s0 + ty + i) * 768 + 512 + e0 + tx];
    __syncthreads();
    long base = (long)n * 1048576;
#pragma unroll
    for (int i = 0; i < 32; i += 8) {
        float v = t[tx][ty + i];
        __nv_bfloat16 h = __float2bfloat16(v);
        long o = base + (long)(e0 + ty + i) * 4096 + s0 + tx;
        g_vth[o] = h;
        g_vtl[o] = __float2bfloat16(v - __bfloat162float(h));
    }
}

// ================= S1 (verified R10) =================
#define S1_STAGE 30720
__global__ __launch_bounds__(256, 2) void s1_mma_k()
{
    extern __shared__ char smc[];
    int tid = threadIdx.x, lane = tid & 31, wid = tid >> 5;
    int wm = wid >> 1, ws = wid & 1, gid = lane >> 2, tg = lane & 3;
    int n = blockIdx.y, i0 = blockIdx.x * 128;
    const __nv_bfloat16* Ah = g_qbh + (long)n * 1048576 + (long)i0 * 256;
    const __nv_bfloat16* Al = g_qbl + (long)n * 1048576 + (long)i0 * 256;
    const __nv_bfloat16* Bh = g_klbh + n * 16384;
    const __nv_bfloat16* Bl = g_klbl + n * 16384;

    float acc[2][4][4];
#pragma unroll
    for (int a = 0; a < 2; a++)
#pragma unroll
        for (int b = 0; b < 4; b++)
#pragma unroll
            for (int c = 0; c < 4; c++) acc[a][b][c] = 0.f;

    auto issue = [&](int c, int buf) {
#pragma unroll
        for (int it = 0; it < 6; it++) {
            int idx = tid + it * 256;
            uint32_t d; const __nv_bfloat16* s;
            if (idx < 1024) {
                int half = idx >> 9, r = (idx >> 2) & 127, seg = idx & 3;
                d = smem_u32(smc + buf * S1_STAGE + half * 10240 + r * 80 + seg * 16);
                s = (half ? Al : Ah) + r * 256 + c * 32 + seg * 8;
            } else {
                int j = idx - 1024;
                int half = j >> 8, r = (j >> 2) & 63, seg = j & 3;
                d = smem_u32(smc + buf * S1_STAGE + 20480 + half * 5120 + r * 80 + seg * 16);
                s = (half ? Bl : Bh) + r * 256 + c * 32 + seg * 8;
            }
            CPA16(d, s);
        }
        CPA_COMMIT();
    };

    issue(0, 0);
    for (int c = 0; c < 8; c++) {
        if (c < 7) { issue(c + 1, (c + 1) & 1); CPA_WAIT1(); }
        else CPA_WAIT0();
        __syncthreads();
        const char* st = smc + (c & 1) * S1_STAGE;
#pragma unroll
        for (int ks = 0; ks < 2; ks++) {
            uint32_t bh[4][2], bl[4][2];
#pragma unroll
            for (int nt = 0; nt < 4; nt++) {
                int nrow = ws * 32 + nt * 8 + gid;
                const char* pb = st + 20480 + nrow * 80 + (ks * 16 + tg * 2) * 2;
                bh[nt][0] = *(const uint32_t*)pb;
                bh[nt][1] = *(const uint32_t*)(pb + 16);
                bl[nt][0] = *(const uint32_t*)(pb + 5120);
                bl[nt][1] = *(const uint32_t*)(pb + 5136);
            }
#pragma unroll
            for (int mt = 0; mt < 2; mt++) {
                int arow = wm * 32 + mt * 16 + gid;
                const char* pa = st + arow * 80 + (ks * 16 + tg * 2) * 2;
                uint32_t ah0 = *(const uint32_t*)pa;
                uint32_t ah1 = *(const uint32_t*)(pa + 640);
                uint32_t ah2 = *(const uint32_t*)(pa + 16);
                uint32_t ah3 = *(const uint32_t*)(pa + 656);
                uint32_t al0 = *(const uint32_t*)(pa + 10240);
                uint32_t al1 = *(const uint32_t*)(pa + 10880);
                uint32_t al2 = *(const uint32_t*)(pa + 10256);
                uint32_t al3 = *(const uint32_t*)(pa + 10896);
#pragma unroll
                for (int nt = 0; nt < 4; nt++) {
                    mma_bf16(acc[mt][nt], ah0, ah1, ah2, ah3, bh[nt][0], bh[nt][1]);
                    mma_bf16(acc[mt][nt], ah0, ah1, ah2, ah3, bl[nt][0], bl[nt][1]);
                    mma_bf16(acc[mt][nt], al0, al1, al2, al3, bh[nt][0], bh[nt][1]);
                }
            }
        }
        __syncthreads();
    }
#pragma unroll
    for (int mt = 0; mt < 2; mt++) {
        int r0 = i0 + wm * 32 + mt * 16 + gid;
#pragma unroll
        for (int nt = 0; nt < 4; nt++) {
            int col = ws * 32 + nt * 8 + tg * 2;
            float* dst = g_S1 + ((long)n * 4096 + r0) * 64 + col;
            *(float2*)dst = make_float2(acc[mt][nt][0], acc[mt][nt][1]);
            *(float2*)(dst + 512) = make_float2(acc[mt][nt][2], acc[mt][nt][3]);
        }
    }
}

// ================= S3 (verified R10) =================
__global__ __launch_bounds__(256, 2) void s3_mma_k()
{
    extern __shared__ char smc[];
    int tid = threadIdx.x, lane = tid & 31, wid = tid >> 5;
    int wm = wid >> 2, ws = wid & 3, gid = lane >> 2, tg = lane & 3;
    int n = blockIdx.y, s0 = blockIdx.x * 128;
    const __nv_bfloat16* Ah = g_qlbh + n * 16384;
    const __nv_bfloat16* Al = g_qlbl + n * 16384;
    const __nv_bfloat16* Bh = g_kbh + (long)n * 1048576 + (long)s0 * 256;
    const __nv_bfloat16* Bl = g_kbl + (long)n * 1048576 + (long)s0 * 256;

    float acc[2][4][4];
#pragma unroll
    for (int a = 0; a < 2; a++)
#pragma unroll
        for (int b = 0; b < 4; b++)
#pragma unroll
            for (int c = 0; c < 4; c++) acc[a][b][c] = 0.f;

    auto issue = [&](int c, int buf) {
#pragma unroll
        for (int it = 0; it < 6; it++) {
            int idx = tid + it * 256;
            uint32_t d; const __nv_bfloat16* s;
            if (idx < 512) {
                int half = idx >> 8, r = (idx >> 2) & 63, seg = idx & 3;
                d = smem_u32(smc + buf * S1_STAGE + half * 5120 + r * 80 + seg * 16);
                s = (half ? Al : Ah) + r * 256 + c * 32 + seg * 8;
            } else {
                int j = idx - 512;
                int half = j >> 9, r = (j >> 2) & 127, seg = j & 3;
                d = smem_u32(smc + buf * S1_STAGE + 10240 + half * 10240 + r * 80 + seg * 16);
                s = (half ? Bl : Bh) + r * 256 + c * 32 + seg * 8;
            }
            CPA16(d, s);
        }
        CPA_COMMIT();
    };

    issue(0, 0);
    for (int c = 0; c < 8; c++) {
        if (c < 7) { issue(c + 1, (c + 1) & 1); CPA_WAIT1(); }
        else CPA_WAIT0();
        __syncthreads();
        const char* st = smc + (c & 1) * S1_STAGE;
#pragma unroll
        for (int ks = 0; ks < 2; ks++) {
            uint32_t bh[4][2], bl[4][2];
#pragma unroll
            for (int nt = 0; nt < 4; nt++) {
                int nrow = ws * 32 + nt * 8 + gid;
                const char* pb = st + 10240 + nrow * 80 + (ks * 16 + tg * 2) * 2;
                bh[nt][0] = *(const uint32_t*)pb;
                bh[nt][1] = *(const uint32_t*)(pb + 16);
                bl[nt][0] = *(const uint32_t*)(pb + 10240);
                bl[nt][1] = *(const uint32_t*)(pb + 10256);
            }
#pragma unroll
            for (int mt = 0; mt < 2; mt++) {
                int arow = wm * 32 + mt * 16 + gid;
                const char* pa = st + arow * 80 + (ks * 16 + tg * 2) * 2;
                uint32_t ah0 = *(const uint32_t*)pa;
                uint32_t ah1 = *(const uint32_t*)(pa + 640);
                uint32_t ah2 = *(const uint32_t*)(pa + 16);
                uint32_t ah3 = *(const uint32_t*)(pa + 656);
                uint32_t al0 = *(const uint32_t*)(pa + 5120);
                uint32_t al1 = *(const uint32_t*)(pa + 5760);
                uint32_t al2 = *(const uint32_t*)(pa + 5136);
                uint32_t al3 = *(const uint32_t*)(pa + 5776);
#pragma unroll
                for (int nt = 0; nt < 4; nt++) {
                    mma_bf16(acc[mt][nt], ah0, ah1, ah2, ah3, bh[nt][0], bh[nt][1]);
                    mma_bf16(acc[mt][nt], ah0, ah1, ah2, ah3, bl[nt][0], bl[nt][1]);
                    mma_bf16(acc[mt][nt], al0, al1, al2, al3, bh[nt][0], bh[nt][1]);
                }
            }
        }
        __syncthreads();
    }
#pragma unroll
    for (int mt = 0; mt < 2; mt++) {
        int r0 = wm * 32 + mt * 16 + gid;
#pragma unroll
        for (int nt = 0; nt < 4; nt++) {
            int col = s0 + ws * 32 + nt * 8 + tg * 2;
            float* dst = g_S3 + (long)n * 262144 + (long)r0 * 4096 + col;
            *(float2*)dst = make_float2(acc[mt][nt][0], acc[mt][nt][1]);
            *(float2*)(dst + 8 * 4096) = make_float2(acc[mt][nt][2], acc[mt][nt][3]);
        }
    }
}

// ================= softmax helpers (S1 column stats) =================
__global__ void colstats_part_k()
{
    __shared__ float sm2[4][64];
    int stripe = blockIdx.x, n = blockIdx.y;
    int tid = threadIdx.x;
    int j = tid & 63, g = tid >> 6;
    const float* S = g_S1 + (long)n * SS * 64;
    float m = -1e30f;
    for (int i = stripe * 512 + g; i < stripe * 512 + 512; i += 4)
        m = fmaxf(m, S[(long)i * 64 + j]);
    sm2[g][j] = m;
    __syncthreads();
    float mm = fmaxf(fmaxf(sm2[0][j], sm2[1][j]), fmaxf(sm2[2][j], sm2[3][j]));
    float s = 0.f;
    for (int i = stripe * 512 + g; i < stripe * 512 + 512; i += 4)
        s += expf(S[(long)i * 64 + j] - mm);
    __syncthreads();
    sm2[g][j] = s;
    __syncthreads();
    if (g == 0) {
        float ss = sm2[0][j] + sm2[1][j] + sm2[2][j] + sm2[3][j];
        g_pmax[(n * 8 + stripe) * 64 + j] = mm;
        g_psum[(n * 8 + stripe) * 64 + j] = ss;
    }
}

__global__ void colstats_comb_k()
{
    int n = blockIdx.x, j = threadIdx.x;
    float m = -1e30f;
#pragma unroll
    for (int c = 0; c < 8; c++) m = fmaxf(m, g_pmax[(n * 8 + c) * 64 + j]);
    float s = 0.f;
#pragma unroll
    for (int c = 0; c < 8; c++)
        s += g_psum[(n * 8 + c) * 64 + j] * expf(g_pmax[(n * 8 + c) * 64 + j] - m);
    g_m[n * 64 + j] = m;
    g_sinv[n * 64 + j] = 1.f / s;
}

// ================= T3 = softmax(S3) @ v  (fused softmax; split-K 8) =================
// smem: Bh 0 (20480), Bl 20480, Ah 40960 (5120), Al 46080, raw 51200 (8192), red 59392
#define T3_SMEM 59648
__global__ __launch_bounds__(256, 2) void t3_mma_k()
{
    extern __shared__ char smc[];
    float* raw = (float*)(smc + 51200);   // [64 j][32 s]
    float* red = (float*)(smc + 59392);   // mx[32], rinv[32]
    int tid = threadIdx.x, lane = tid & 31, wid = tid >> 5;
    int wm = wid >> 2, ws = wid & 3, gid = lane >> 2, tg = lane & 3;
    int n = blockIdx.y, s0 = blockIdx.x * 512;

    float acc[2][8][4];
#pragma unroll
    for (int a = 0; a < 2; a++)
#pragma unroll
        for (int b = 0; b < 8; b++)
#pragma unroll
            for (int c = 0; c < 4; c++) acc[a][b][c] = 0.f;

    int jrow = tid >> 2, kq = (tid & 3) * 8;
    for (int cc = 0; cc < 16; cc++) {
        int sc = s0 + cc * 32;
        // B cp.async (vT rows), overlap with softmax
#pragma unroll
        for (int it = 0; it < 8; it++) {
            int idx = tid + it * 256;
            int half = idx >> 10, r = (idx >> 2) & 255, seg = idx & 3;
            uint32_t d = smem_u32(smc + half * 20480 + r * 80 + seg * 16);
            const __nv_bfloat16* s = (half ? g_vtl : g_vth) +
                (long)n * 1048576 + (long)r * 4096 + sc + seg * 8;
            CPA16(d, s);
        }
        CPA_COMMIT();
        // stage raw S3 chunk
        float v[8];
        {
            const float* s = g_S3 + (long)n * 262144 + (long)jrow * 4096 + sc + kq;
            *(float4*)&v[0] = *(const float4*)s;
            *(float4*)&v[4] = *(const float4*)(s + 4);
            *(float4*)&raw[jrow * 32 + kq] = *(float4*)&v[0];
            *(float4*)&raw[jrow * 32 + kq + 4] = *(float4*)&v[4];
        }
        __syncthreads();
        // per-column softmax stats over j (32 workers)
        if (tid < 32) {
            int s = tid;
            float m = -1e30f;
#pragma unroll 8
            for (int j = 0; j < 64; j++) m = fmaxf(m, raw[j * 32 + s]);
            float sum = 0.f;
#pragma unroll 8
            for (int j = 0; j < 64; j++) sum += expf(raw[j * 32 + s] - m);
            red[s] = m; red[32 + s] = 1.f / sum;
        }
        __syncthreads();
        // convert A = exp(v - mx) * rinv, split hi/lo
        {
            uint32_t hi[4], lo[4];
#pragma unroll
            for (int p = 0; p < 4; p++) {
                float e0 = expf(v[2 * p] - red[kq + 2 * p]) * red[32 + kq + 2 * p];
                float e1 = expf(v[2 * p + 1] - red[kq + 2 * p + 1]) * red[32 + kq + 2 * p + 1];
                __nv_bfloat16 h0 = __float2bfloat16(e0);
                __nv_bfloat16 h1 = __float2bfloat16(e1);
                hi[p] = pack2(__bfloat162float(h0), __bfloat162float(h1));
                lo[p] = pack2(e0 - __bfloat162float(h0), e1 - __bfloat162float(h1));
            }
            *(uint4*)(smc + 40960 + jrow * 80 + (kq >> 3) * 16) = *(uint4*)hi;
            *(uint4*)(smc + 46080 + jrow * 80 + (kq >> 3) * 16) = *(uint4*)lo;
        }
        CPA_WAIT0();
        __syncthreads();
#pragma unroll
        for (int ks = 0; ks < 2; ks++) {
            uint32_t bh[8][2], bl[8][2];
#pragma unroll
            for (int nt = 0; nt < 8; nt++) {
                int nrow = ws * 64 + nt * 8 + gid;
                const char* pb = smc + nrow * 80 + (ks * 16 + tg * 2) * 2;
                bh[nt][0] = *(const uint32_t*)pb;
                bh[nt][1] = *(const uint32_t*)(pb + 16);
                bl[nt][0] = *(const uint32_t*)(pb + 20480);
                bl[nt][1] = *(const uint32_t*)(pb + 20496);
            }
#pragma unroll
            for (int mt = 0; mt < 2; mt++) {
                int arow = wm * 32 + mt * 16 + gid;
                const char* pa = smc + 40960 + arow * 80 + (ks * 16 + tg * 2) * 2;
                uint32_t ah0 = *(const uint32_t*)pa;
                uint32_t ah1 = *(const uint32_t*)(pa + 640);
                uint32_t ah2 = *(const uint32_t*)(pa + 16);
                uint32_t ah3 = *(const uint32_t*)(pa + 656);
                uint32_t al0 = *(const uint32_t*)(pa + 5120);
                uint32_t al1 = *(const uint32_t*)(pa + 5760);
                uint32_t al2 = *(const uint32_t*)(pa + 5136);
                uint32_t al3 = *(const uint32_t*)(pa + 5776);
#pragma unroll
                for (int nt = 0; nt < 8; nt++) {
                    mma_bf16(acc[mt][nt], ah0, ah1, ah2, ah3, bh[nt][0], bh[nt][1]);
                    mma_bf16(acc[mt][nt], ah0, ah1, ah2, ah3, bl[nt][0], bl[nt][1]);
                    mma_bf16(acc[mt][nt], al0, al1, al2, al3, bh[nt][0], bh[nt][1]);
                }
            }
        }
        __syncthreads();
    }
    float* dst = g_T3p + (long)(n * 8 + blockIdx.x) * 16384;
#pragma unroll
    for (int mt = 0; mt < 2; mt++) {
        int r0 = wm * 32 + mt * 16 + gid;
#pragma unroll
        for (int nt = 0; nt < 8; nt++) {
            int col = ws * 64 + nt * 8 + tg * 2;
            *(float2*)(dst + r0 * 256 + col) = make_float2(acc[mt][nt][0], acc[mt][nt][1]);
            *(float2*)(dst + (r0 + 8) * 256 + col) = make_float2(acc[mt][nt][2], acc[mt][nt][3]);
        }
    }
}

__global__ void t3_reduce_k()
{
    int idx = blockIdx.x * 256 + threadIdx.x;
    int n = idx >> 14;
    int r = idx & 16383;
    const float* p = g_T3p + (long)n * 8 * 16384 + r;
    float s = 0.f;
#pragma unroll
    for (int c = 0; c < 8; c++) s += p[(long)c * 16384];
    g_T3[idx] = s;
}

// ================= k2inv v2 (verified R13) =================
#define KV_K2   0
#define KV_VV   4096
#define KV_BA   8192
#define KV_BB   12288
#define KV_BC   16384
#define KV_P    20480
#define KV_QLS  32768
#define KV_KTS  34816
#define KV_RED  36992
#define KV_T3S  8192
#define K2INV_SMEM_FLOATS 37184

__device__ __forceinline__ void mm64v2(float* D, const float* A, const float* B,
                                       float* P, int tid)
{
    int kg = tid >> 8;
    int t = tid & 255;
    int r0 = (t >> 4) * 4;
    int c0 = (t & 15) * 4;
    int kb = kg * 16;
    float acc[4][4];
#pragma unroll
    for (int a = 0; a < 4; a++)
#pragma unroll
        for (int b = 0; b < 4; b++) acc[a][b] = 0.f;

#pragma unroll
    for (int kk = 0; kk < 16; kk += 4) {
        float4 av[4];
#pragma unroll
        for (int rr = 0; rr < 4; rr++)
            av[rr] = *(const float4*)&A[(r0 + rr) * 64 + kb + kk];
#pragma unroll
        for (int kq = 0; kq < 4; kq++) {
            float4 b = *(const float4*)&B[(kb + kk + kq) * 64 + c0];
#pragma unroll
            for (int rr = 0; rr < 4; rr++) {
                float aw = reinterpret_cast<const float*>(&av[rr])[kq];
                acc[rr][0] += aw * b.x; acc[rr][1] += aw * b.y;
                acc[rr][2] += aw * b.z; acc[rr][3] += aw * b.w;
            }
        }
    }
    if (kg) {
        float* Pp = P + (kg - 1) * 4096;
#pragma unroll
        for (int rr = 0; rr < 4; rr++)
            *(float4*)&Pp[(r0 + rr) * 64 + c0] =
                make_float4(acc[rr][0], acc[rr][1], acc[rr][2], acc[rr][3]);
    }
    __syncthreads();
    if (kg == 0) {
#pragma unroll
        for (int rr = 0; rr < 4; rr++) {
            float4 s = make_float4(acc[rr][0], acc[rr][1], acc[rr][2], acc[rr][3]);
#pragma unroll
            for (int g = 0; g < 3; g++) {
                float4 p = *(const float4*)&P[g * 4096 + (r0 + rr) * 64 + c0];
                s.x += p.x; s.y += p.y; s.z += p.z; s.w += p.w;
            }
            *(float4*)&D[(r0 + rr) * 64 + c0] = s;
        }
    }
    __syncthreads();
}

__global__ __launch_bounds__(1024) void k2inv_k()
{
    extern __shared__ float sm[];
    float* K2 = sm + KV_K2;
    float* Vv = sm + KV_VV;
    float* BA = sm + KV_BA;
    float* BB = sm + KV_BB;
    float* BC = sm + KV_BC;
    float* P  = sm + KV_P;
    float* QLs = sm + KV_QLS;
    float* KTs = sm + KV_KTS;
    float* red = sm + KV_RED;

    int n = blockIdx.x;
    int tid = threadIdx.x;
    const float* ql = g_qland + n * 16384;
    const float* kl = g_kland + n * 16384;

    int st = tid & 255;
    int sr0 = (st >> 4) * 4;
    int sc0 = (st & 15) * 4;
    float accS[4][4];
#pragma unroll
    for (int a = 0; a < 4; a++)
#pragma unroll
        for (int b = 0; b < 4; b++) accS[a][b] = 0.f;

    for (int e0 = 0; e0 < 256; e0 += 32) {
#pragma unroll
        for (int p = 0; p < 2; p++) {
            int t2 = tid + p * 1024;
            int r = t2 >> 5, c = t2 & 31;
            QLs[r * 32 + c] = ql[r * 256 + e0 + c];
            KTs[c * 68 + r] = kl[r * 256 + e0 + c];
        }
        __syncthreads();
        if (tid < 256) {
#pragma unroll
            for (int kk = 0; kk < 32; kk += 4) {
                float4 av[4];
#pragma unroll
                for (int rr = 0; rr < 4; rr++)
                    av[rr] = *(const float4*)&QLs[(sr0 + rr) * 32 + kk];
#pragma unroll
                for (int kq = 0; kq < 4; kq++) {
                    float4 b = *(const float4*)&KTs[(kk + kq) * 68 + sc0];
#pragma unroll
                    for (int rr = 0; rr < 4; rr++) {
                        float aw = reinterpret_cast<const float*>(&av[rr])[kq];
                        accS[rr][0] += aw * b.x; accS[rr][1] += aw * b.y;
                        accS[rr][2] += aw * b.z; accS[rr][3] += aw * b.w;
                    }
                }
            }
        }
        __syncthreads();
    }
    if (tid < 256) {
#pragma unroll
        for (int rr = 0; rr < 4; rr++)
            *(float4*)&K2[(sr0 + rr) * 64 + sc0] =
                make_float4(accS[rr][0], accS[rr][1], accS[rr][2], accS[rr][3]);
    }
    __syncthreads();

    if (tid < 64) {
        int j = tid;
        float m = -1e30f;
        for (int i = 0; i < 64; i++) m = fmaxf(m, K2[i * 64 + j]);
        float s = 0.f;
        for (int i = 0; i < 64; i++) s += expf(K2[i * 64 + j] - m);
        red[j] = m; red[64 + j] = 1.f / s;
    }
    __syncthreads();
#pragma unroll
    for (int p = 0; p < 4; p++) {
        int t = tid + p * 1024;
        int j = t & 63;
        K2[t] = expf(K2[t] - red[j]) * red[64 + j];
    }
    __syncthreads();

    if (tid < 64) {
        int i = tid;
        float rs = 0.f, cs = 0.f;
        for (int j = 0; j < 64; j++) { rs += fabsf(K2[i * 64 + j]); cs += fabsf(K2[j * 64 + i]); }
        red[i] = rs; red[64 + i] = cs;
    }
    __syncthreads();
    if (tid == 0) {
        float vi = 0.f, v0 = 0.f;
        for (int t = 0; t < 64; t++) { vi = fmaxf(vi, red[t]); v0 = fmaxf(v0, red[64 + t]); }
        red[128] = 1.f / (v0 * vi);
    }
    __syncthreads();
    float isc = red[128];
#pragma unroll
    for (int p = 0; p < 4; p++) {
        int t = tid + p * 1024;
        int a = t >> 6, b = t & 63;
        Vv[t] = K2[b * 64 + a] * isc;
    }
    __syncthreads();

    for (int it = 0; it < 6; it++) {
        mm64v2(BA, K2, Vv, P, tid);
        mm64v2(BB, BA, BA, P, tid);
#pragma unroll
        for (int p = 0; p < 4; p++) {
            int t = tid + p * 1024;
            float d = ((t >> 6) == (t & 63)) ? 15.f : 0.f;
            BB[t] = d - 7.f * BA[t] + BB[t];
        }
        __syncthreads();
        mm64v2(BC, BA, BB, P, tid);
#pragma unroll
        for (int p = 0; p < 4; p++) {
            int t = tid + p * 1024;
            float d = ((t >> 6) == (t & 63)) ? 13.f : 0.f;
            BC[t] = d - BC[t];
        }
        __syncthreads();
        mm64v2(BB, Vv, BC, P, tid);
#pragma unroll
        for (int p = 0; p < 4; p++) {
            int t = tid + p * 1024;
            Vv[t] = 0.25f * BB[t];
        }
        __syncthreads();
    }

    float* T3s = sm + KV_T3S;
    for (int it = 0; it < 16; it++) {
        int idx = tid + it * 1024;
        T3s[idx] = g_T3[n * 16384 + idx];
    }
    __syncthreads();
    {
        int g = tid >> 8, t = tid & 255;
        int j0 = (t >> 4) * 4;
        int ec0 = g * 64 + (t & 15) * 4;
        float acc[4][4];
#pragma unroll
        for (int a = 0; a < 4; a++)
#pragma unroll
            for (int b = 0; b < 4; b++) acc[a][b] = 0.f;
#pragma unroll
        for (int kk = 0; kk < 64; kk += 4) {
            float4 av[4];
#pragma unroll
            for (int rr = 0; rr < 4; rr++)
                av[rr] = *(const float4*)&Vv[(j0 + rr) * 64 + kk];
#pragma unroll
            for (int kq = 0; kq < 4; kq++) {
                float4 b = *(const float4*)&T3s[(kk + kq) * 256 + ec0];
#pragma unroll
                for (int rr = 0; rr < 4; rr++) {
                    float aw = reinterpret_cast<const float*>(&av[rr])[kq];
                    acc[rr][0] += aw * b.x; acc[rr][1] += aw * b.y;
                    acc[rr][2] += aw * b.z; acc[rr][3] += aw * b.w;
                }
            }
        }
#pragma unroll
        for (int rr = 0; rr < 4; rr++) {
            float sv = g_sinv[n * 64 + j0 + rr];
#pragma unroll
            for (int cc = 0; cc < 4; cc++) {
                float a = acc[rr][cc] * sv;
                __nv_bfloat16 h = __float2bfloat16(a);
                long o = (long)n * 16384 + (long)(ec0 + cc) * 64 + j0 + rr;
                g_M2h[o] = h;
                g_M2l[o] = __float2bfloat16(a - __bfloat162float(h));
            }
        }
    }
}

// ================= out = exp(S1-m)@M2 + v, write bf16 hi/lo [e2][s2] =================
#define OUT_SMEM 61696
__global__ __launch_bounds__(256, 1) void out_mma_k()
{
    extern __shared__ char smc[];
    float* ms = (float*)smc;
    int tid = threadIdx.x, lane = tid & 31, wid = tid >> 5;
    int wm = wid >> 2, ws = wid & 3, gid = lane >> 2, tg = lane & 3;
    int n = blockIdx.y, i0 = blockIdx.x * 128;

    if (tid < 64) ms[tid] = g_m[n * 64 + tid];
    __syncthreads();

    float acc[4][8][4];
#pragma unroll
    for (int a = 0; a < 4; a++)
#pragma unroll
        for (int b = 0; b < 8; b++)
#pragma unroll
            for (int c = 0; c < 4; c++) acc[a][b][c] = 0.f;

    for (int c = 0; c < 2; c++) {
        if (c) __syncthreads();
        {
            int row = tid >> 1, kq = (tid & 1) * 16;
            const float* Sr = g_S1 + ((long)n * 4096 + i0 + row) * 64 + c * 32 + kq;
            float v[16];
            *(float4*)&v[0]  = *(const float4*)Sr;
            *(float4*)&v[4]  = *(const float4*)(Sr + 4);
            *(float4*)&v[8]  = *(const float4*)(Sr + 8);
            *(float4*)&v[12] = *(const float4*)(Sr + 12);
            uint32_t hi[8], lo[8];
#pragma unroll
            for (int p = 0; p < 8; p++) {
                float e0 = expf(v[2 * p] - ms[c * 32 + kq + 2 * p]);
                float e1 = expf(v[2 * p + 1] - ms[c * 32 + kq + 2 * p + 1]);
                __nv_bfloat16 h0 = __float2bfloat16(e0), h1 = __float2bfloat16(e1);
                hi[p] = pack2(__bfloat162float(h0), __bfloat162float(h1));
                lo[p] = pack2(e0 - __bfloat162float(h0), e1 - __bfloat162float(h1));
            }
            char* pa = smc + 256 + row * 80 + (kq >> 3) * 16;
            *(uint4*)pa = *(uint4*)hi;
            *(uint4*)(pa + 16) = *(uint4*)&hi[4];
            char* pl = smc + 10496 + row * 80 + (kq >> 3) * 16;
            *(uint4*)pl = *(uint4*)lo;
            *(uint4*)(pl + 16) = *(uint4*)&lo[4];
        }
#pragma unroll
        for (int it = 0; it < 8; it++) {
            int idx = tid + it * 256;
            int half = idx >> 10, r = (idx >> 2) & 255, seg = idx & 3;
            uint32_t d = smem_u32(smc + 20736 + half * 20480 + r * 80 + seg * 16);
            const __nv_bfloat16* s = (half ? g_M2l : g_M2h) + n * 16384 + r * 64 + c * 32 + seg * 8;
            CPA16(d, s);
        }
        CPA_COMMIT();
        CPA_WAIT0();
        __syncthreads();
#pragma unroll
        for (int ks = 0; ks < 2; ks++) {
            uint32_t bh[8][2], bl[8][2];
#pragma unroll
            for (int nt = 0; nt < 8; nt++) {
                int nrow = ws * 64 + nt * 8 + gid;
                const char* pb = smc + 20736 + nrow * 80 + (ks * 16 + tg * 2) * 2;
                bh[nt][0] = *(const uint32_t*)pb;
                bh[nt][1] = *(const uint32_t*)(pb + 16);
                bl[nt][0] = *(const uint32_t*)(pb + 20480);
                bl[nt][1] = *(const uint32_t*)(pb + 20496);
            }
#pragma unroll
            for (int mt = 0; mt < 4; mt++) {
                int arow = wm * 64 + mt * 16 + gid;
                const char* pa = smc + 256 + arow * 80 + (ks * 16 + tg * 2) * 2;
                uint32_t ah0 = *(const uint32_t*)pa;
                uint32_t ah1 = *(const uint32_t*)(pa + 640);
                uint32_t ah2 = *(const uint32_t*)(pa + 16);
                uint32_t ah3 = *(const uint32_t*)(pa + 656);
                uint32_t al0 = *(const uint32_t*)(pa + 10240);
                uint32_t al1 = *(const uint32_t*)(pa + 10880);
                uint32_t al2 = *(const uint32_t*)(pa + 10256);
                uint32_t al3 = *(const uint32_t*)(pa + 10896);
#pragma unroll
                for (int nt = 0; nt < 8; nt++) {
                    mma_bf16(acc[mt][nt], ah0, ah1, ah2, ah3, bh[nt][0], bh[nt][1]);
                    mma_bf16(acc[mt][nt], ah0, ah1, ah2, ah3, bl[nt][0], bl[nt][1]);
                    mma_bf16(acc[mt][nt], al0, al1, al2, al3, bh[nt][0], bh[nt][1]);
                }
            }
        }
    }

    const float* vb = g_Y + (long)n * QKV * SS + 512;
    __nv_bfloat16* obh = g_obh + (long)n * 1048576;
    __nv_bfloat16* obl = g_obl + (long)n * 1048576;
#pragma unroll
    for (int mt = 0; mt < 4; mt++) {
        int r0 = i0 + wm * 64 + mt * 16 + gid;
#pragma unroll
        for (int nt = 0; nt < 8; nt++) {
            int col = ws * 64 + nt * 8 + tg * 2;
            float2 v0 = *(const float2*)(vb + (long)r0 * 768 + col);
            float2 v1 = *(const float2*)(vb + (long)(r0 + 8) * 768 + col);
#pragma unroll
            for (int h = 0; h < 2; h++) {
                int ri = r0 + h * 8;
                float x0 = acc[mt][nt][2 * h] + (h ? v1.x : v0.x);
                float x1 = acc[mt][nt][2 * h + 1] + (h ? v1.y : v0.y);
                __nv_bfloat16 h0 = __float2bfloat16(x0), h1 = __float2bfloat16(x1);
                long o = (long)(ri >> 4) * 4096 + (ri & 15) * 256 + col;
                *(uint32_t*)(obh + o) = pack2(__bfloat162float(h0), __bfloat162float(h1));
                *(uint32_t*)(obl + o) = pack2(x0 - __bfloat162float(h0), x1 - __bfloat162float(h1));
            }
        }
    }
}

// ---------------- host ----------------
extern "C" void kernel_launch(void* const* d_in, const int* in_sizes, int n_in,
                              void* d_out, int out_size)
{
    const float* x     = (const float*)d_in[0];
    const float* w_qkv = (const float*)d_in[1];
    const float* b_qkv = (const float*)d_in[2];
    const float* w_out = (const float*)d_in[3];
    const float* b_out = (const float*)d_in[4];
    float* out = (float*)d_out;

    cudaFuncSetAttribute(k2inv_k, cudaFuncAttributeMaxDynamicSharedMemorySize,
                         K2INV_SMEM_FLOATS * (int)sizeof(float));
    cudaFuncSetAttribute(mma_gemm_k, cudaFuncAttributeMaxDynamicSharedMemorySize, MG_SMEM);
    cudaFuncSetAttribute(mma_gemm_bt, cudaFuncAttributeMaxDynamicSharedMemorySize, BT_SMEM);
    cudaFuncSetAttribute(s1_mma_k, cudaFuncAttributeMaxDynamicSharedMemorySize, 2 * S1_STAGE);
    cudaFuncSetAttribute(s3_mma_k, cudaFuncAttributeMaxDynamicSharedMemorySize, 2 * S1_STAGE);
    cudaFuncSetAttribute(t3_mma_k, cudaFuncAttributeMaxDynamicSharedMemorySize, T3_SMEM);
    cudaFuncSetAttribute(out_mma_k, cudaFuncAttributeMaxDynamicSharedMemorySize, OUT_SMEM);

    void *yb;
    cudaGetSymbolAddress(&yb, g_Y);
    void *wqh, *wql, *woh, *wol, *xh, *xl, *obh, *obl;
    cudaGetSymbolAddress(&wqh, g_wqh); cudaGetSymbolAddress(&wql, g_wql);
    cudaGetSymbolAddress(&woh, g_woh); cudaGetSymbolAddress(&wol, g_wol);
    cudaGetSymbolAddress(&xh, g_xh);   cudaGetSymbolAddress(&xl, g_xl);
    cudaGetSymbolAddress(&obh, g_obh); cudaGetSymbolAddress(&obl, g_obl);

    // 0) operand conversion
    cvt_w_k<<<768, 256>>>(w_qkv, (__nv_bfloat16*)wqh, (__nv_bfloat16*)wql, QKV * 256);
    cvt_w_k<<<256, 256>>>(w_out, (__nv_bfloat16*)woh, (__nv_bfloat16*)wol, 256 * 256);
    tcvt_k<<<dim3(128, 8, NB), dim3(32, 8)>>>(x, (__nv_bfloat16*)xh, (__nv_bfloat16*)xl,
                                              (long)1048576);

    // 1) qkv projection
    mma_gemm_k<<<dim3(32, 6, NB), 256, MG_SMEM>>>(
        (const __nv_bfloat16*)wqh, (const __nv_bfloat16*)wql,
        (const __nv_bfloat16*)xh, (const __nv_bfloat16*)xl,
        (float*)yb, b_qkv, (long)SS * 256, (long)QKV * SS);

    // 2) fused q/k converts + landmarks; vT transpose convert
    qkland_k<<<dim3(NB, 64), 256>>>();
    vtcvt_k<<<dim3(128, 8, NB), dim3(32, 8)>>>();

    // 3) attention GEMMs (softmax for S3 fused into t3)
    s1_mma_k<<<dim3(32, NB), 256, 2 * S1_STAGE>>>();
    colstats_part_k<<<dim3(8, NB), 256>>>();
    colstats_comb_k<<<NB, 64>>>();
    s3_mma_k<<<dim3(32, NB), 256, 2 * S1_STAGE>>>();
    t3_mma_k<<<dim3(8, NB), 256, T3_SMEM>>>();
    t3_reduce_k<<<512, 256>>>();
    k2inv_k<<<NB, 1024, K2INV_SMEM_FLOATS * (int)sizeof(float)>>>();
    out_mma_k<<<dim3(32, NB), 256, OUT_SMEM>>>();

    // 4) output projection directly from bf16 [k][s] O (ldmatrix.trans B path)
    mma_gemm_bt<<<dim3(32, 2, NB), 256, BT_SMEM>>>(
        (const __nv_bfloat16*)woh, (const __nv_bfloat16*)wol,
        (const __nv_bfloat16*)obh, (const __nv_bfloat16*)obl,
        out, b_out, (long)1048576, (long)256 * SS);
}